// round 2
// baseline (speedup 1.0000x reference)
#include <cuda_runtime.h>
#include <cstdint>
#include <cmath>

typedef unsigned long long u64;

#define NT 128                  // threads per CTA (4 warps)
#define PM 2288                 // floats per muscle block in smem (non-dup, transposed)
#define OFF_W1 0                // 3*32
#define OFF_B1 96               // 32
#define OFF_W2 128              // 32*32
#define OFF_B2 1152             // 32
#define OFF_W3 1184             // 32*32
#define OFF_B3 2208             // 32
#define OFF_W4 2240             // 32
#define OFF_B4 2272             // 1
#define OFF_PAR 2273            // 7 scalars: K0,K1,L0,L1,Ms,Ms2,K1L1
#define SCR_F (8*PM)            // scratch starts after weights (18304 floats = 73216 B)
#define SMEM_BYTES (SCR_F*4 + 64*NT*8)   // + 4 slots * 16 u64 * NT = 64KB scratch
#define DTC 0.0166667f
#define NNR 0.3f

// ---------- packed f32x2 helpers ----------
__device__ __forceinline__ u64 fma2(u64 a, u64 b, u64 c) {
    u64 d; asm("fma.rn.f32x2 %0, %1, %2, %3;" : "=l"(d) : "l"(a), "l"(b), "l"(c)); return d;
}
__device__ __forceinline__ u64 mul2(u64 a, u64 b) {
    u64 d; asm("mul.rn.f32x2 %0, %1, %2;" : "=l"(d) : "l"(a), "l"(b)); return d;
}
__device__ __forceinline__ u64 add2(u64 a, u64 b) {
    u64 d; asm("add.rn.f32x2 %0, %1, %2;" : "=l"(d) : "l"(a), "l"(b)); return d;
}
__device__ __forceinline__ u64 pack2(float lo, float hi) {
    u64 r; asm("mov.b64 %0, {%1, %2};" : "=l"(r) : "r"(__float_as_uint(lo)), "r"(__float_as_uint(hi))); return r;
}
__device__ __forceinline__ void unpack2(u64 v, float& lo, float& hi) {
    unsigned a, b; asm("mov.b64 {%0, %1}, %2;" : "=r"(a), "=r"(b) : "l"(v));
    lo = __uint_as_float(a); hi = __uint_as_float(b);
}
__device__ __forceinline__ float tanh_ap(float x) {
    float y; asm("tanh.approx.f32 %0, %1;" : "=f"(y) : "f"(x)); return y;
}
// leaky_relu(x) = 0.505*x + 0.495*|x|  (slope 0.01 on negatives), packed, elementwise
__device__ __forceinline__ u64 leaky2(u64 x, u64 c505, u64 c495) {
    u64 ax = x & 0x7FFFFFFF7FFFFFFFull;
    return fma2(x, c505, mul2(ax, c495));
}

// 32->32 layer for 4 batch slots; activations packed by OUTPUT pairs {o,o+1}.
// scratch layout: u64 scr[(q*16 + pair)*NT + tid]
__device__ __forceinline__ void layer32_p4(const float* __restrict__ mbW,
                                           const float* __restrict__ mbB,
                                           u64* __restrict__ scr, int tid,
                                           u64 c505, u64 c495) {
    u64 acc[4][16];
    {
        const ulonglong2* bp = reinterpret_cast<const ulonglong2*>(mbB);
#pragma unroll
        for (int j = 0; j < 8; j++) {
            ulonglong2 b = bp[j];
#pragma unroll
            for (int q = 0; q < 4; q++) { acc[q][2*j] = b.x; acc[q][2*j+1] = b.y; }
        }
    }
#pragma unroll 2
    for (int ip = 0; ip < 16; ip++) {
        float2 h[4];
#pragma unroll
        for (int q = 0; q < 4; q++)
            h[q] = *reinterpret_cast<const float2*>(&scr[(q*16 + ip) * NT + tid]);
        u64 hl[4], hh[4];
#pragma unroll
        for (int q = 0; q < 4; q++) { hl[q] = pack2(h[q].x, h[q].x); hh[q] = pack2(h[q].y, h[q].y); }
        const ulonglong2* w0 = reinterpret_cast<const ulonglong2*>(mbW + (2*ip)   * 32);
        const ulonglong2* w1 = reinterpret_cast<const ulonglong2*>(mbW + (2*ip+1) * 32);
#pragma unroll
        for (int j = 0; j < 8; j++) {
            ulonglong2 a0 = w0[j];
#pragma unroll
            for (int q = 0; q < 4; q++) {
                acc[q][2*j]   = fma2(hl[q], a0.x, acc[q][2*j]);
                acc[q][2*j+1] = fma2(hl[q], a0.y, acc[q][2*j+1]);
            }
            ulonglong2 a1 = w1[j];
#pragma unroll
            for (int q = 0; q < 4; q++) {
                acc[q][2*j]   = fma2(hh[q], a1.x, acc[q][2*j]);
                acc[q][2*j+1] = fma2(hh[q], a1.y, acc[q][2*j+1]);
            }
        }
    }
#pragma unroll
    for (int q = 0; q < 4; q++)
#pragma unroll
        for (int p = 0; p < 16; p++)
            scr[(q*16 + p) * NT + tid] = leaky2(acc[q][p], c505, c495);
}

// closed-form 2x2 expm + phi1 solve for one element (validated R1, rel_err 5.7e-7)
__device__ __forceinline__ void finalize(float Ks, float Bs, float s0, float s1,
                                         float Iv, float invI, float Bv, float Kv,
                                         float& o0, float& o1) {
    float A10 = -(Ks + Kv) * invI;
    float Dd  = 2.0f * sqrtf(fmaxf(Ks * Iv, 0.0f));
    float A11 = -(Dd + Bv) * invI;
    float B10 = Bs * invI;
    float a10 = A10 * DTC, a11 = A11 * DTC;
    float s = 0.5f * a11;
    float q = fmaf(s, s, DTC * a10);
    float c, kf;
    if (q >= 0.0f) {
        float w = sqrtf(q);
        c = coshf(w);
        kf = (w > 1e-4f) ? sinhf(w) / w : 1.0f + q * (1.0f / 6.0f);
    } else {
        float w = sqrtf(-q);
        c = __cosf(w);
        kf = (w > 1e-4f) ? __sinf(w) / w : 1.0f + q * (1.0f / 6.0f);
    }
    float es = __expf(s);
    float g  = es * fmaf(-s, kf, c);
    float kk = es * kf;
    float Ad01 = kk * DTC;
    float Ad10 = kk * a10;
    float Ad11 = g + kk * a11;
    float v  = DTC * B10;
    float y1 = kk * v;
    float r1 = (Ad11 - 1.0f) * v;
    float y0 = (r1 - a11 * y1) / a10;
    o0 = fmaf(g,    s0, fmaf(Ad01, s1, y0));
    o1 = fmaf(Ad10, s0, fmaf(Ad11, s1, y1));
}

__global__ __launch_bounds__(NT, 1)
void joint_kernel(const float* __restrict__ SS,  const float* __restrict__ AL,
                  const float* __restrict__ K0,  const float* __restrict__ K1,
                  const float* __restrict__ L0,  const float* __restrict__ L1,
                  const float* __restrict__ Ms,  const float* __restrict__ Ip,
                  const float* __restrict__ Bvp, const float* __restrict__ Kvp,
                  const float* __restrict__ W1,  const float* __restrict__ b1,
                  const float* __restrict__ W2,  const float* __restrict__ b2,
                  const float* __restrict__ W3,  const float* __restrict__ b3,
                  const float* __restrict__ W4,  const float* __restrict__ b4,
                  float* __restrict__ out, int B) {
    extern __shared__ float sm[];
    const int tid = threadIdx.x;

    // ---- build transposed (NON-duplicated) weight tables in smem ----
    for (int t = tid; t < 768; t += NT) {            // W1[m][o][i] -> [m][i][o]
        int m = t / 96, r = t - m * 96, o = r / 3, i = r - o * 3;
        sm[m * PM + OFF_W1 + i * 32 + o] = W1[t];
    }
    for (int t = tid; t < 8192; t += NT) {           // W2[m][o][i] -> [m][i][o]
        int m = t >> 10, r = t & 1023, o = r >> 5, i = r & 31;
        sm[m * PM + OFF_W2 + i * 32 + o] = W2[t];
    }
    for (int t = tid; t < 8192; t += NT) {           // W3
        int m = t >> 10, r = t & 1023, o = r >> 5, i = r & 31;
        sm[m * PM + OFF_W3 + i * 32 + o] = W3[t];
    }
    for (int t = tid; t < 256; t += NT) {            // W4[m][0][i]
        int m = t >> 5, i = t & 31;
        sm[m * PM + OFF_W4 + i] = W4[t];
    }
    for (int t = tid; t < 256; t += NT) {            // b1
        int m = t >> 5, o = t & 31;
        sm[m * PM + OFF_B1 + o] = b1[t];
    }
    for (int t = tid; t < 256; t += NT) {            // b2
        int m = t >> 5, o = t & 31;
        sm[m * PM + OFF_B2 + o] = b2[t];
    }
    for (int t = tid; t < 256; t += NT) {            // b3
        int m = t >> 5, o = t & 31;
        sm[m * PM + OFF_B3 + o] = b3[t];
    }
    if (tid < 8) {
        int m = tid;
        sm[m * PM + OFF_B4] = b4[m];
        float k0 = K0[m], k1 = K1[m], l0 = L0[m], l1 = L1[m], ms = Ms[m];
        float* p = sm + m * PM + OFF_PAR;
        p[0] = k0; p[1] = k1; p[2] = l0; p[3] = l1;
        p[4] = ms; p[5] = ms * ms; p[6] = k1 * l1;
    }
    __syncthreads();

    const int t0 = blockIdx.x * NT + tid;
    const int base = t0 * 4;
    if (base >= B) return;

    int e[4];
#pragma unroll
    for (int q = 0; q < 4; q++) e[q] = (base + q < B) ? base + q : B - 1;

    const u64 c505 = pack2(0.505f, 0.505f);
    const u64 c495 = pack2(0.495f, 0.495f);

    const float Iv = __ldg(Ip), Bv = __ldg(Bvp), Kv = __ldg(Kvp);
    const float invI = 1.0f / Iv;

    float2 ss[4];
#pragma unroll
    for (int q = 0; q < 4; q++) ss[q] = reinterpret_cast<const float2*>(SS)[e[q]];

    u64* scr = reinterpret_cast<u64*>(sm + SCR_F);

    float Ksum[4] = {0.f, 0.f, 0.f, 0.f};
    float Bsum[4] = {0.f, 0.f, 0.f, 0.f};

#pragma unroll 1
    for (int m = 0; m < 8; m++) {
        const float* mb = sm + m * PM;
        const float* par = mb + OFF_PAR;
        const float K0v = par[0], K1v = par[1], L0v = par[2], L1v = par[3];
        const float Msv = par[4], Ms2v = par[5], K1L1v = par[6];

        float a[4], l[4];
        u64 x0[4], x1[4], x2[4];
#pragma unroll
        for (int q = 0; q < 4; q++) {
            a[q] = fminf(fmaxf(__ldg(&AL[(size_t)e[q] * 8 + m]), 0.0f), 1.0f);
            l[q] = ss[q].x * Msv;
            float dl = ss[q].y * Msv;
            x0[q] = pack2(l[q], l[q]);
            x1[q] = pack2(dl, dl);
            x2[q] = pack2(a[q], a[q]);
        }

        // ---- layer 1 (3 -> 32), outputs packed {o,o+1} ----
        {
            u64 acc[4][16];
            const ulonglong2* bp = reinterpret_cast<const ulonglong2*>(mb + OFF_B1);
#pragma unroll
            for (int j = 0; j < 8; j++) {
                ulonglong2 b = bp[j];
#pragma unroll
                for (int q = 0; q < 4; q++) { acc[q][2*j] = b.x; acc[q][2*j+1] = b.y; }
            }
#pragma unroll
            for (int i = 0; i < 3; i++) {
                const ulonglong2* wp = reinterpret_cast<const ulonglong2*>(mb + OFF_W1 + i * 32);
#pragma unroll
                for (int j = 0; j < 8; j++) {
                    ulonglong2 w = wp[j];
#pragma unroll
                    for (int q = 0; q < 4; q++) {
                        u64 x = (i == 0) ? x0[q] : (i == 1) ? x1[q] : x2[q];
                        acc[q][2*j]   = fma2(x, w.x, acc[q][2*j]);
                        acc[q][2*j+1] = fma2(x, w.y, acc[q][2*j+1]);
                    }
                }
            }
#pragma unroll
            for (int q = 0; q < 4; q++)
#pragma unroll
                for (int p = 0; p < 16; p++)
                    scr[(q*16 + p) * NT + tid] = leaky2(acc[q][p], c505, c495);
        }

        // ---- layers 2,3 (32 -> 32) ----
        layer32_p4(mb + OFF_W2, mb + OFF_B2, scr, tid, c505, c495);
        layer32_p4(mb + OFF_W3, mb + OFF_B3, scr, tid, c505, c495);

        // ---- layer 4 (32 -> 1) + tanh: packed dot over input pairs ----
        {
            const float b4v = mb[OFF_B4];
            const u64* w4 = reinterpret_cast<const u64*>(mb + OFF_W4);
            float nn[4];
#pragma unroll
            for (int q = 0; q < 4; q++) {
                u64 s0 = 0ull, s1 = 0ull;
#pragma unroll
                for (int ip = 0; ip < 16; ip += 2) {
                    s0 = fma2(scr[(q*16 + ip)     * NT + tid], w4[ip],     s0);
                    s1 = fma2(scr[(q*16 + ip + 1) * NT + tid], w4[ip + 1], s1);
                }
                u64 sm2 = add2(s0, s1);
                float lo, hi; unpack2(sm2, lo, hi);
                nn[q] = NNR * tanh_ap(lo + hi + b4v);
            }

            // ---- muscle epilogue (scalar per slot) ----
#pragma unroll
            for (int q = 0; q < 4; q++) {
                float K = fmaf(a[q], K1v, K0v);
                Ksum[q] = fmaf(K, Ms2v, Ksum[q]);
                float tL = fmaf(a[q], L1v, L0v) - fabsf(l[q]);
                float BF = fmaf(a[q] * a[q] * nn[q], K1L1v, K * tL);
                Bsum[q] = fmaf(BF, Msv, Bsum[q]);
            }
        }
    }

    // ---- per-element expm epilogue + stores ----
    float2* seg2 = reinterpret_cast<float2*>(out + B);
#pragma unroll
    for (int q = 0; q < 4; q++) {
        float o0, o1;
        finalize(Ksum[q], Bsum[q], ss[q].x, ss[q].y, Iv, invI, Bv, Kv, o0, o1);
        out[e[q]]  = o0;
        seg2[e[q]] = make_float2(o0, o1);
    }
}

extern "C" void kernel_launch(void* const* d_in, const int* in_sizes, int n_in,
                              void* d_out, int out_size) {
    const float* SS  = (const float*)d_in[0];
    const float* AL  = (const float*)d_in[1];
    const float* K0  = (const float*)d_in[2];
    const float* K1  = (const float*)d_in[3];
    const float* L0  = (const float*)d_in[4];
    const float* L1  = (const float*)d_in[5];
    const float* Ms  = (const float*)d_in[6];
    const float* Ip  = (const float*)d_in[7];
    const float* Bv  = (const float*)d_in[8];
    const float* Kv  = (const float*)d_in[9];
    const float* W1  = (const float*)d_in[10];
    const float* b1  = (const float*)d_in[11];
    const float* W2  = (const float*)d_in[12];
    const float* b2  = (const float*)d_in[13];
    const float* W3  = (const float*)d_in[14];
    const float* b3  = (const float*)d_in[15];
    const float* W4  = (const float*)d_in[16];
    const float* b4  = (const float*)d_in[17];
    float* out = (float*)d_out;

    const int B = in_sizes[0] / 2;
    const int threads = (B + 3) / 4;
    const int grid = (threads + NT - 1) / NT;

    cudaFuncSetAttribute(joint_kernel, cudaFuncAttributeMaxDynamicSharedMemorySize, SMEM_BYTES);
    joint_kernel<<<grid, NT, SMEM_BYTES>>>(SS, AL, K0, K1, L0, L1, Ms, Ip, Bv, Kv,
                                           W1, b1, W2, b2, W3, b3, W4, b4, out, B);
}

// round 3
// speedup vs baseline: 2.2541x; 2.2541x over previous
#include <cuda_runtime.h>
#include <cstdint>
#include <cmath>

typedef unsigned long long u64;

#define NT 224                  // 7 warps per CTA, 1 CTA/SM, grid=147
#define PM 2344                 // floats per muscle block in smem
#define OFF_W1T 0               // 3*32 transposed [i][o]
#define OFF_B1P 96              // 32  (native b1: pairs {b_2o,b_2o+1})
#define OFF_W2  128             // 32*32 NATIVE [o][i]
#define OFF_B2Z 1152            // 64  ({b_o, 0} interleaved)
#define OFF_W3  1216            // 32*32 NATIVE [o][i]
#define OFF_B3Z 2240            // 64
#define OFF_W4  2304            // 32 native [i]
#define OFF_B4  2336            // 1
#define OFF_PAR 2337            // 7: K0,K1,L0,L1,Ms,Ms2,K1L1
#define SMEM_BYTES (8*PM*4)
#define DTC 0.0166667f
#define NNR 0.3f

// ---------- packed f32x2 helpers ----------
__device__ __forceinline__ u64 fma2(u64 a, u64 b, u64 c) {
    u64 d; asm("fma.rn.f32x2 %0, %1, %2, %3;" : "=l"(d) : "l"(a), "l"(b), "l"(c)); return d;
}
__device__ __forceinline__ u64 add2(u64 a, u64 b) {
    u64 d; asm("add.rn.f32x2 %0, %1, %2;" : "=l"(d) : "l"(a), "l"(b)); return d;
}
__device__ __forceinline__ u64 mul2(u64 a, u64 b) {
    u64 d; asm("mul.rn.f32x2 %0, %1, %2;" : "=l"(d) : "l"(a), "l"(b)); return d;
}
__device__ __forceinline__ u64 pack2(float lo, float hi) {
    u64 r; asm("mov.b64 %0, {%1, %2};" : "=l"(r) : "r"(__float_as_uint(lo)), "r"(__float_as_uint(hi))); return r;
}
__device__ __forceinline__ void unpack2(u64 v, float& lo, float& hi) {
    unsigned a, b; asm("mov.b64 {%0, %1}, %2;" : "=r"(a), "=r"(b) : "l"(v));
    lo = __uint_as_float(a); hi = __uint_as_float(b);
}
__device__ __forceinline__ float tanh_ap(float x) {
    float y; asm("tanh.approx.f32 %0, %1;" : "=f"(y) : "f"(x)); return y;
}
// packed leaky (elementwise): 0.505x + 0.495|x|
__device__ __forceinline__ u64 leaky2(u64 x, u64 c505, u64 c495) {
    u64 ax = x & 0x7FFFFFFF7FFFFFFFull;
    return fma2(x, c505, mul2(ax, c495));
}
// scalar leaky
__device__ __forceinline__ float leakys(float x) {
    return fmaf(0.505f, x, 0.495f * fabsf(x));
}

// closed-form 2x2 expm + phi1 solve (validated: rel_err 5.7e-7)
__device__ __forceinline__ void finalize(float Ks, float Bs, float s0, float s1,
                                         float Iv, float invI, float Bv, float Kv,
                                         float& o0, float& o1) {
    float A10 = -(Ks + Kv) * invI;
    float Dd  = 2.0f * sqrtf(fmaxf(Ks * Iv, 0.0f));
    float A11 = -(Dd + Bv) * invI;
    float B10 = Bs * invI;
    float a10 = A10 * DTC, a11 = A11 * DTC;
    float s = 0.5f * a11;
    float q = fmaf(s, s, DTC * a10);
    float c, kf;
    if (q >= 0.0f) {
        float w = sqrtf(q);
        c = coshf(w);
        kf = (w > 1e-4f) ? sinhf(w) / w : 1.0f + q * (1.0f / 6.0f);
    } else {
        float w = sqrtf(-q);
        c = __cosf(w);
        kf = (w > 1e-4f) ? __sinf(w) / w : 1.0f + q * (1.0f / 6.0f);
    }
    float es = __expf(s);
    float g  = es * fmaf(-s, kf, c);
    float kk = es * kf;
    float Ad01 = kk * DTC;
    float Ad10 = kk * a10;
    float Ad11 = g + kk * a11;
    float v  = DTC * B10;
    float y1 = kk * v;
    float r1 = (Ad11 - 1.0f) * v;
    float y0 = (r1 - a11 * y1) / a10;
    o0 = fmaf(g,    s0, fmaf(Ad01, s1, y0));
    o1 = fmaf(Ad10, s0, fmaf(Ad11, s1, y1));
}

__global__ __launch_bounds__(NT, 1)
void joint_kernel(const float* __restrict__ SS,  const float* __restrict__ AL,
                  const float* __restrict__ K0,  const float* __restrict__ K1,
                  const float* __restrict__ L0,  const float* __restrict__ L1,
                  const float* __restrict__ Ms,  const float* __restrict__ Ip,
                  const float* __restrict__ Bvp, const float* __restrict__ Kvp,
                  const float* __restrict__ W1,  const float* __restrict__ b1,
                  const float* __restrict__ W2,  const float* __restrict__ b2,
                  const float* __restrict__ W3,  const float* __restrict__ b3,
                  const float* __restrict__ W4,  const float* __restrict__ b4,
                  float* __restrict__ out, int B) {
    extern __shared__ float sm[];
    const int tid = threadIdx.x;

    // ---- smem tables ----
    for (int t = tid; t < 768; t += NT) {            // W1[m][o][i] -> [m][i][o]
        int m = t / 96, r = t - m * 96, o = r / 3, i = r - o * 3;
        sm[m * PM + OFF_W1T + i * 32 + o] = W1[t];
    }
    for (int t = tid; t < 256; t += NT) {            // b1 native (pairs over o)
        int m = t >> 5, o = t & 31;
        sm[m * PM + OFF_B1P + o] = b1[t];
    }
    {                                                // W2, W3 native copies (float4)
        const float4* s2 = reinterpret_cast<const float4*>(W2);
        const float4* s3 = reinterpret_cast<const float4*>(W3);
        for (int t = tid; t < 2048; t += NT) {
            int m = t >> 8, r = t & 255;
            *reinterpret_cast<float4*>(&sm[m * PM + OFF_W2 + r * 4]) = s2[t];
            *reinterpret_cast<float4*>(&sm[m * PM + OFF_W3 + r * 4]) = s3[t];
        }
    }
    for (int t = tid; t < 512; t += NT) {            // b2, b3 as {b, 0} interleaved
        int m = t >> 6, r = t & 63;
        float v2 = (r & 1) ? 0.0f : b2[m * 32 + (r >> 1)];
        float v3 = (r & 1) ? 0.0f : b3[m * 32 + (r >> 1)];
        sm[m * PM + OFF_B2Z + r] = v2;
        sm[m * PM + OFF_B3Z + r] = v3;
    }
    for (int t = tid; t < 256; t += NT) {            // W4 native
        int m = t >> 5, i = t & 31;
        sm[m * PM + OFF_W4 + i] = W4[t];
    }
    if (tid < 8) {
        int m = tid;
        sm[m * PM + OFF_B4] = b4[m];
        float k0 = K0[m], k1 = K1[m], l0 = L0[m], l1 = L1[m], ms = Ms[m];
        float* p = sm + m * PM + OFF_PAR;
        p[0] = k0; p[1] = k1; p[2] = l0; p[3] = l1;
        p[4] = ms; p[5] = ms * ms; p[6] = k1 * l1;
    }
    __syncthreads();

    const int base = (blockIdx.x * NT + tid) * 2;
    if (base >= B) return;
    const int e0 = base;
    const int e1 = (base + 1 < B) ? base + 1 : B - 1;

    const u64 c505 = pack2(0.505f, 0.505f);
    const u64 c495 = pack2(0.495f, 0.495f);

    const float Iv = __ldg(Ip), Bv = __ldg(Bvp), Kv = __ldg(Kvp);
    const float invI = 1.0f / Iv;

    const float2 ssA = reinterpret_cast<const float2*>(SS)[e0];
    const float2 ssB = reinterpret_cast<const float2*>(SS)[e1];

    float Ksum[2] = {0.f, 0.f};
    float Bsum[2] = {0.f, 0.f};

#pragma unroll 1
    for (int m = 0; m < 8; m++) {
        const float* mb = sm + m * PM;
        const float* par = mb + OFF_PAR;
        const float K0v = par[0], K1v = par[1], L0v = par[2], L1v = par[3];
        const float Msv = par[4], Ms2v = par[5], K1L1v = par[6];

        float a0 = fminf(fmaxf(__ldg(&AL[(size_t)e0 * 8 + m]), 0.0f), 1.0f);
        float a1 = fminf(fmaxf(__ldg(&AL[(size_t)e1 * 8 + m]), 0.0f), 1.0f);
        float l0v = ssA.x * Msv, l1v = ssB.x * Msv;
        u64 xl[2] = { pack2(l0v, l0v),          pack2(l1v, l1v) };
        u64 xd[2] = { pack2(ssA.y * Msv, ssA.y * Msv), pack2(ssB.y * Msv, ssB.y * Msv) };
        u64 xa[2] = { pack2(a0, a0),            pack2(a1, a1) };

        // ---- layer 1 (3 -> 32): produce hp[q][p] = {h_2p, h_2p+1} ----
        u64 hp[2][16];
        {
            const u64* b1p = reinterpret_cast<const u64*>(mb + OFF_B1P);
            const u64* w0r = reinterpret_cast<const u64*>(mb + OFF_W1T);
            const u64* w1r = reinterpret_cast<const u64*>(mb + OFF_W1T + 32);
            const u64* w2r = reinterpret_cast<const u64*>(mb + OFF_W1T + 64);
#pragma unroll
            for (int p = 0; p < 16; p++) {
                u64 w0 = w0r[p], w1 = w1r[p], w2 = w2r[p], bb = b1p[p];
                u64 acc0 = fma2(xl[0], w0, bb);
                u64 acc1 = fma2(xl[1], w0, bb);
                acc0 = fma2(xd[0], w1, acc0);
                acc1 = fma2(xd[1], w1, acc1);
                acc0 = fma2(xa[0], w2, acc0);
                acc1 = fma2(xa[1], w2, acc1);
                hp[0][p] = leaky2(acc0, c505, c495);
                hp[1][p] = leaky2(acc1, c505, c495);
            }
        }

        // ---- layers 2 & 3 (32 -> 32), parity-split accumulation ----
#pragma unroll 1
        for (int L = 0; L < 2; L++) {
            const float* W  = mb + (L ? OFF_W3 : OFF_W2);
            const u64*  BZ  = reinterpret_cast<const u64*>(mb + (L ? OFF_B3Z : OFF_B2Z));
            u64 hn[2][16];
#pragma unroll
            for (int og = 0; og < 8; og++) {                 // 4 output rows per group
                const float* wr = W + og * 128;
                u64 acc[8];
#pragma unroll
                for (int r = 0; r < 4; r++) { u64 b = BZ[og * 4 + r]; acc[r] = b; acc[4 + r] = b; }
#pragma unroll
                for (int ip = 0; ip < 16; ip += 2) {
                    ulonglong2 w0 = *reinterpret_cast<const ulonglong2*>(wr +  0 + ip * 2);
                    ulonglong2 w1 = *reinterpret_cast<const ulonglong2*>(wr + 32 + ip * 2);
                    ulonglong2 w2 = *reinterpret_cast<const ulonglong2*>(wr + 64 + ip * 2);
                    ulonglong2 w3 = *reinterpret_cast<const ulonglong2*>(wr + 96 + ip * 2);
                    acc[0] = fma2(hp[0][ip], w0.x, acc[0]);
                    acc[1] = fma2(hp[0][ip], w1.x, acc[1]);
                    acc[2] = fma2(hp[0][ip], w2.x, acc[2]);
                    acc[3] = fma2(hp[0][ip], w3.x, acc[3]);
                    acc[4] = fma2(hp[1][ip], w0.x, acc[4]);
                    acc[5] = fma2(hp[1][ip], w1.x, acc[5]);
                    acc[6] = fma2(hp[1][ip], w2.x, acc[6]);
                    acc[7] = fma2(hp[1][ip], w3.x, acc[7]);
                    acc[0] = fma2(hp[0][ip+1], w0.y, acc[0]);
                    acc[1] = fma2(hp[0][ip+1], w1.y, acc[1]);
                    acc[2] = fma2(hp[0][ip+1], w2.y, acc[2]);
                    acc[3] = fma2(hp[0][ip+1], w3.y, acc[3]);
                    acc[4] = fma2(hp[1][ip+1], w0.y, acc[4]);
                    acc[5] = fma2(hp[1][ip+1], w1.y, acc[5]);
                    acc[6] = fma2(hp[1][ip+1], w2.y, acc[6]);
                    acc[7] = fma2(hp[1][ip+1], w3.y, acc[7]);
                }
#pragma unroll
                for (int q = 0; q < 2; q++) {
                    float x0, y0, x1, y1;
                    unpack2(acc[q*4+0], x0, y0);
                    unpack2(acc[q*4+1], x1, y1);
                    hn[q][og*2]   = pack2(leakys(x0 + y0), leakys(x1 + y1));
                    unpack2(acc[q*4+2], x0, y0);
                    unpack2(acc[q*4+3], x1, y1);
                    hn[q][og*2+1] = pack2(leakys(x0 + y0), leakys(x1 + y1));
                }
            }
#pragma unroll
            for (int p = 0; p < 16; p++) { hp[0][p] = hn[0][p]; hp[1][p] = hn[1][p]; }
        }

        // ---- layer 4 (32 -> 1) + tanh ----
        const u64* w4p = reinterpret_cast<const u64*>(mb + OFF_W4);
        const float b4v = mb[OFF_B4];
        float nn[2];
#pragma unroll
        for (int q = 0; q < 2; q++) {
            u64 sA = 0ull, sB = 0ull;
#pragma unroll
            for (int ip = 0; ip < 16; ip += 2) {
                sA = fma2(hp[q][ip],   w4p[ip],   sA);
                sB = fma2(hp[q][ip+1], w4p[ip+1], sB);
            }
            u64 s = add2(sA, sB);
            float lo, hi; unpack2(s, lo, hi);
            nn[q] = NNR * tanh_ap(lo + hi + b4v);
        }

        // ---- muscle epilogue ----
        {
            float K = fmaf(a0, K1v, K0v);
            Ksum[0] = fmaf(K, Ms2v, Ksum[0]);
            float tL = fmaf(a0, L1v, L0v) - fabsf(l0v);
            float BF = fmaf(a0 * a0 * nn[0], K1L1v, K * tL);
            Bsum[0] = fmaf(BF, Msv, Bsum[0]);
        }
        {
            float K = fmaf(a1, K1v, K0v);
            Ksum[1] = fmaf(K, Ms2v, Ksum[1]);
            float tL = fmaf(a1, L1v, L0v) - fabsf(l1v);
            float BF = fmaf(a1 * a1 * nn[1], K1L1v, K * tL);
            Bsum[1] = fmaf(BF, Msv, Bsum[1]);
        }
    }

    // ---- per-element expm epilogue + stores ----
    float2* seg2 = reinterpret_cast<float2*>(out + B);
    float o0, o1;
    finalize(Ksum[0], Bsum[0], ssA.x, ssA.y, Iv, invI, Bv, Kv, o0, o1);
    out[e0]  = o0;
    seg2[e0] = make_float2(o0, o1);
    finalize(Ksum[1], Bsum[1], ssB.x, ssB.y, Iv, invI, Bv, Kv, o0, o1);
    out[e1]  = o0;
    seg2[e1] = make_float2(o0, o1);
}

extern "C" void kernel_launch(void* const* d_in, const int* in_sizes, int n_in,
                              void* d_out, int out_size) {
    const float* SS  = (const float*)d_in[0];
    const float* AL  = (const float*)d_in[1];
    const float* K0  = (const float*)d_in[2];
    const float* K1  = (const float*)d_in[3];
    const float* L0  = (const float*)d_in[4];
    const float* L1  = (const float*)d_in[5];
    const float* Ms  = (const float*)d_in[6];
    const float* Ip  = (const float*)d_in[7];
    const float* Bv  = (const float*)d_in[8];
    const float* Kv  = (const float*)d_in[9];
    const float* W1  = (const float*)d_in[10];
    const float* b1  = (const float*)d_in[11];
    const float* W2  = (const float*)d_in[12];
    const float* b2  = (const float*)d_in[13];
    const float* W3  = (const float*)d_in[14];
    const float* b3  = (const float*)d_in[15];
    const float* W4  = (const float*)d_in[16];
    const float* b4  = (const float*)d_in[17];
    float* out = (float*)d_out;

    const int B = in_sizes[0] / 2;
    const int pairs = (B + 1) / 2;
    const int grid = (pairs + NT - 1) / NT;

    cudaFuncSetAttribute(joint_kernel, cudaFuncAttributeMaxDynamicSharedMemorySize, SMEM_BYTES);
    joint_kernel<<<grid, NT, SMEM_BYTES>>>(SS, AL, K0, K1, L0, L1, Ms, Ip, Bv, Kv,
                                           W1, b1, W2, b2, W3, b3, W4, b4, out, B);
}